// round 4
// baseline (speedup 1.0000x reference)
#include <cuda_runtime.h>
#include <cstdint>

#define B_  4
#define L_  2048
#define H_  8
#define D_  64
#define NS  40
#define NBH (B_*H_)
#define NQBLK 8
#define KC  4          // key chunks
#define KCW 512        // keys per chunk

__device__ int    g_idx[L_*NS];
__device__ int    g_lst[L_*NS];      // per-q samples, bucketed by chunk (stable)
__device__ int    g_qoff[L_*(KC+1)]; // per-q chunk offsets
__device__ float2 g_pM[NBH*L_*KC];   // per-(bh,q,chunk) partial (max, sum)
__device__ int    g_top[NBH*NS];
__device__ __align__(16) float g_vmean[NBH*D_];
__device__ __align__(16) float g_vpart[NBH*8*D_];

// ---------------- threefry2x32 ----------------
__device__ __forceinline__ uint32_t rotl32(uint32_t x, int r) {
    return (x << r) | (x >> (32 - r));
}
__device__ __forceinline__ void threefry2x32(uint32_t k0, uint32_t k1,
                                             uint32_t c0, uint32_t c1,
                                             uint32_t& o0, uint32_t& o1) {
    uint32_t ks0 = k0, ks1 = k1, ks2 = k0 ^ k1 ^ 0x1BD11BDAu;
    uint32_t x0 = c0 + ks0, x1 = c1 + ks1;
#define TF_RND(R) { x0 += x1; x1 = rotl32(x1, R); x1 ^= x0; }
    TF_RND(13) TF_RND(15) TF_RND(26) TF_RND(6)  x0 += ks1; x1 += ks2 + 1u;
    TF_RND(17) TF_RND(29) TF_RND(16) TF_RND(24) x0 += ks2; x1 += ks0 + 2u;
    TF_RND(13) TF_RND(15) TF_RND(26) TF_RND(6)  x0 += ks0; x1 += ks1 + 3u;
    TF_RND(17) TF_RND(29) TF_RND(16) TF_RND(24) x0 += ks1; x1 += ks2 + 4u;
    TF_RND(13) TF_RND(15) TF_RND(26) TF_RND(6)  x0 += ks2; x1 += ks0 + 5u;
#undef TF_RND
    o0 = x0; o1 = x1;
}

// K0: partitionable threefry randint
__global__ void kernel_idx() {
    int i = blockIdx.x * blockDim.x + threadIdx.x;
    if (i >= L_ * NS) return;
    uint32_t k20, k21;
    threefry2x32(0u, 42u, 0u, 1u, k20, k21);
    uint32_t a, b;
    threefry2x32(k20, k21, 0u, (uint32_t)i, a, b);
    g_idx[i] = (int)((a ^ b) & 2047u);
}

// K0b: stable counting-sort of each q's 40 samples by key-chunk
__global__ void kernel_sortidx() {
    int qi = blockIdx.x * blockDim.x + threadIdx.x;
    if (qi >= L_) return;
    int cnt[KC] = {0, 0, 0, 0};
    for (int s = 0; s < NS; s++) cnt[g_idx[qi * NS + s] >> 9]++;
    int off[KC + 1];
    off[0] = 0;
    for (int c = 0; c < KC; c++) off[c + 1] = off[c] + cnt[c];
    for (int c = 0; c <= KC; c++) g_qoff[qi * (KC + 1) + c] = off[c];
    int pos[KC] = {off[0], off[1], off[2], off[3]};
    for (int s = 0; s < NS; s++) {
        int j = g_idx[qi * NS + s];
        g_lst[qi * NS + pos[j >> 9]++] = j;
    }
}

// K1: chunked sampled-dot partials. Block = (b,h,kc). K chunk in smem.
__global__ void kernel_M(const float* __restrict__ q, const float* __restrict__ k) {
    extern __shared__ float sK[];   // KCW * 64 floats = 128KB
    int kc = blockIdx.x & 3;
    int h  = (blockIdx.x >> 2) & 7;
    int b  = blockIdx.x >> 5;
    int t  = threadIdx.x;           // 512

    const float4* k4 = (const float4*)k;
    for (int e = t; e < KCW * 16; e += 512) {
        int rr = e >> 4, c = e & 15;
        ((float4*)sK)[e] = __ldg(&k4[(((size_t)(b * L_ + kc * KCW + rr)) * H_ + h) * 16 + c]);
    }
    __syncthreads();

    int warp = t >> 5, lane = t & 31;
    int g = lane >> 3, r = lane & 7;
    int bh = b * H_ + h;

    for (int qi = warp * 128; qi < warp * 128 + 128; qi++) {
        const float4* qr = (const float4*)(q + (((size_t)(b * L_ + qi)) * H_ + h) * D_);
        float4 qa = __ldg(&qr[r]), qb = __ldg(&qr[r + 8]);

        int off = g_qoff[qi * (KC + 1) + kc];
        int end = g_qoff[qi * (KC + 1) + kc + 1];
        int cnt = end - off;

        int lv0 = 0, lv1 = 0;
        if (lane < cnt)      lv0 = g_lst[qi * NS + off + lane];
        if (lane < cnt - 32) lv1 = g_lst[qi * NS + off + 32 + lane];

        float mx = -INFINITY, sm = 0.0f;
        for (int it = 0; it * 4 < cnt; it++) {
            int sidx = it * 4 + g;
            int j = (sidx < 32) ? __shfl_sync(0xffffffffu, lv0, sidx)
                                : __shfl_sync(0xffffffffu, lv1, sidx - 32);
            bool act = sidx < cnt;
            int jl = act ? (j - kc * KCW) : 0;
            const float4* kr = (const float4*)(sK + jl * 64);
            float4 ka = kr[r], kb = kr[r + 8];
            float p = ka.x * qa.x + ka.y * qa.y + ka.z * qa.z + ka.w * qa.w
                    + kb.x * qb.x + kb.y * qb.y + kb.z * qb.z + kb.w * qb.w;
            p += __shfl_xor_sync(0xffffffffu, p, 4);
            p += __shfl_xor_sync(0xffffffffu, p, 2);
            p += __shfl_xor_sync(0xffffffffu, p, 1);
            if (act) { mx = fmaxf(mx, p); sm += p; }
        }
        // combine 4 sample-groups
        mx = fmaxf(mx, __shfl_xor_sync(0xffffffffu, mx, 8));
        mx = fmaxf(mx, __shfl_xor_sync(0xffffffffu, mx, 16));
        sm += __shfl_xor_sync(0xffffffffu, sm, 8);
        sm += __shfl_xor_sync(0xffffffffu, sm, 16);
        if (lane == 0) g_pM[((size_t)bh * L_ + qi) * KC + kc] = make_float2(mx, sm);
    }
}

// K2: top-40 per (b,h); combines chunk partials at load. Tie-break lower index.
__global__ void kernel_topk() {
    int bh = blockIdx.x, t = threadIdx.x;   // 256 threads
    float vals[8];
#pragma unroll
    for (int i = 0; i < 8; i++) {
        int qi = t * 8 + i;
        const float2* pp = &g_pM[((size_t)bh * L_ + qi) * KC];
        float2 p0 = pp[0], p1 = pp[1], p2 = pp[2], p3 = pp[3];
        float mx = fmaxf(fmaxf(p0.x, p1.x), fmaxf(p2.x, p3.x));
        float sm = p0.y + p1.y + p2.y + p3.y;
        vals[i] = mx - sm * (1.0f / (float)NS);
    }

    __shared__ float wv[8];
    __shared__ int   wi[8];
    __shared__ int   sbi;
    int warp = t >> 5, lane = t & 31;

    for (int u = 0; u < NS; u++) {
        float bv = -INFINITY; int bi = 1 << 30;
#pragma unroll
        for (int i = 0; i < 8; i++) {
            if (vals[i] > bv) { bv = vals[i]; bi = t * 8 + i; }
        }
#pragma unroll
        for (int o = 16; o; o >>= 1) {
            float ov = __shfl_xor_sync(0xffffffffu, bv, o);
            int   oi = __shfl_xor_sync(0xffffffffu, bi, o);
            if (ov > bv || (ov == bv && oi < bi)) { bv = ov; bi = oi; }
        }
        if (lane == 0) { wv[warp] = bv; wi[warp] = bi; }
        __syncthreads();
        if (t == 0) {
            float fb = wv[0]; int fi = wi[0];
#pragma unroll
            for (int wd = 1; wd < 8; wd++) {
                if (wv[wd] > fb || (wv[wd] == fb && wi[wd] < fi)) { fb = wv[wd]; fi = wi[wd]; }
            }
            g_top[bh * NS + u] = fi;
            sbi = fi;
        }
        __syncthreads();
        int fi = sbi;
        if ((fi >> 3) == t) vals[fi & 7] = -INFINITY;
        __syncthreads();
    }
}

// K3a: V_mean partials
__global__ void kernel_vmean(const float* __restrict__ v) {
    int bh = blockIdx.x >> 3, c = blockIdx.x & 7;
    int b = bh >> 3, h = bh & 7;
    int t = threadIdx.x;
    int d4 = t & 15, r = t >> 4;

    const float4* v4 = (const float4*)v;
    size_t base = ((size_t)b * L_) * (H_ * D_ / 4) + h * (D_ / 4) + d4;
    float4 acc = make_float4(0.f, 0.f, 0.f, 0.f);
#pragma unroll 4
    for (int i = 0; i < 16; i++) {
        int l = c * 256 + i * 16 + r;
        float4 x = __ldg(&v4[base + (size_t)l * (H_ * D_ / 4)]);
        acc.x += x.x; acc.y += x.y; acc.z += x.z; acc.w += x.w;
    }
    __shared__ float4 sred[256];
    sred[t] = acc;
    __syncthreads();
    if (t < 16) {
        float4 s = sred[t];
#pragma unroll
        for (int rr = 1; rr < 16; rr++) {
            float4 x = sred[rr * 16 + t];
            s.x += x.x; s.y += x.y; s.z += x.z; s.w += x.w;
        }
        ((float4*)g_vpart)[(bh * 8 + c) * 16 + t] = s;
    }
}

// K3b: reduce partials -> g_vmean
__global__ void kernel_vmean_final() {
    int i = blockIdx.x * blockDim.x + threadIdx.x;   // 2048
    int bh = i >> 6, d = i & 63;
    float s = 0.0f;
#pragma unroll
    for (int c = 0; c < 8; c++) s += g_vpart[(bh * 8 + c) * 64 + d];
    g_vmean[i] = s * (1.0f / (float)L_);
}

// K3c: broadcast V_mean into output
__global__ void kernel_init(float* __restrict__ out) {
    int i = blockIdx.x * blockDim.x + threadIdx.x;   // float4 units, 1M
    int d4  = i & 15;
    int row = i >> 4;
    int h   = row & 7;
    int b   = row >> 14;
    float4 vm = ((const float4*)g_vmean)[(b * H_ + h) * 16 + d4];
    ((float4*)out)[i] = vm;
}

// K4: dense attention for 40 selected queries. 512 threads/block.
__global__ void kernel_update(const float* __restrict__ q, const float* __restrict__ k,
                              const float* __restrict__ v, float* __restrict__ out) {
    extern __shared__ float sh[];
    float* s_sc  = sh;                    // NQBLK * L_
    float* s_q   = s_sc + NQBLK * L_;     // NQBLK * D_
    float* s_red = s_q + NQBLK * D_;      // 512

    const int groups = NS / NQBLK;        // 5
    int bx  = blockIdx.x;
    int bh  = bx / groups;
    int grp = bx % groups;
    int b = bh >> 3, h = bh & 7;
    int t = threadIdx.x;                  // 512

    int qidx[NQBLK];
#pragma unroll
    for (int i = 0; i < NQBLK; i++) qidx[i] = g_top[bh * NS + grp * NQBLK + i];

    for (int e = t; e < NQBLK * D_; e += 512) {
        int i = e >> 6, d = e & 63;
        s_q[e] = q[(((size_t)(b * L_ + qidx[i])) * H_ + h) * D_ + d];
    }
    __syncthreads();

    const float4* k4 = (const float4*)k;
    const float4* q4 = (const float4*)s_q;
#pragma unroll 1
    for (int rep = 0; rep < L_ / 512; rep++) {
        int j = rep * 512 + t;
        const float4* kr = k4 + (((size_t)(b * L_ + j)) * H_ + h) * (D_ / 4);
        float acc[NQBLK];
#pragma unroll
        for (int i = 0; i < NQBLK; i++) acc[i] = 0.0f;
#pragma unroll
        for (int dv = 0; dv < D_ / 4; dv++) {
            float4 kv = __ldg(&kr[dv]);
#pragma unroll
            for (int i = 0; i < NQBLK; i++) {
                float4 qv = q4[i * (D_ / 4) + dv];
                acc[i] += kv.x * qv.x + kv.y * qv.y + kv.z * qv.z + kv.w * qv.w;
            }
        }
#pragma unroll
        for (int i = 0; i < NQBLK; i++) s_sc[i * L_ + j] = acc[i] * 0.125f;
    }
    __syncthreads();

    for (int i = 0; i < NQBLK; i++) {
        float* sc = s_sc + i * L_;
        float m = -INFINITY;
        for (int j = t; j < L_; j += 512) m = fmaxf(m, sc[j]);
        s_red[t] = m; __syncthreads();
        for (int o = 256; o; o >>= 1) { if (t < o) s_red[t] = fmaxf(s_red[t], s_red[t + o]); __syncthreads(); }
        float gmax = s_red[0];
        __syncthreads();
        float ssum = 0.0f;
        for (int j = t; j < L_; j += 512) { float e = __expf(sc[j] - gmax); sc[j] = e; ssum += e; }
        s_red[t] = ssum; __syncthreads();
        for (int o = 256; o; o >>= 1) { if (t < o) s_red[t] += s_red[t + o]; __syncthreads(); }
        float inv = 1.0f / s_red[0];
        __syncthreads();
        for (int j = t; j < L_; j += 512) sc[j] *= inv;
        __syncthreads();
    }

    int d = t & 63, c = t >> 6;
    float accs[NQBLK];
#pragma unroll
    for (int i = 0; i < NQBLK; i++) accs[i] = 0.0f;
    const float* vb = v + ((size_t)b * L_ * H_) * D_ + h * D_ + d;
    for (int j = c * 256; j < c * 256 + 256; j++) {
        float vv = __ldg(&vb[(size_t)j * (H_ * D_)]);
#pragma unroll
        for (int i = 0; i < NQBLK; i++) accs[i] += s_sc[i * L_ + j] * vv;
    }
    for (int i = 0; i < NQBLK; i++) {
        s_red[t] = accs[i];
        __syncthreads();
        if (t < 64) {
            float tot = 0.0f;
#pragma unroll
            for (int cc = 0; cc < 8; cc++) tot += s_red[cc * 64 + t];
            out[(((size_t)(b * L_ + qidx[i])) * H_ + h) * D_ + t] = tot;
        }
        __syncthreads();
    }
}

extern "C" void kernel_launch(void* const* d_in, const int* in_sizes, int n_in,
                              void* d_out, int out_size) {
    const float* q = (const float*)d_in[0];
    const float* k = (const float*)d_in[1];
    const float* v = (const float*)d_in[2];
    float* out = (float*)d_out;

    static const size_t upd_smem = (size_t)(NQBLK * L_ + NQBLK * D_ + 512) * sizeof(float);
    static const size_t m_smem = (size_t)(KCW * D_) * sizeof(float);   // 128KB
    cudaFuncSetAttribute(kernel_update, cudaFuncAttributeMaxDynamicSharedMemorySize, (int)upd_smem);
    cudaFuncSetAttribute(kernel_M, cudaFuncAttributeMaxDynamicSharedMemorySize, (int)m_smem);

    kernel_idx<<<(L_ * NS + 255) / 256, 256>>>();
    kernel_sortidx<<<(L_ + 255) / 256, 256>>>();
    kernel_vmean<<<NBH * 8, 256>>>(v);
    kernel_vmean_final<<<8, 256>>>();
    kernel_init<<<(B_ * L_ * H_ * D_ / 4) / 256, 256>>>(out);
    kernel_M<<<B_ * H_ * KC, 512, m_smem>>>(q, k);
    kernel_topk<<<NBH, 256>>>();
    kernel_update<<<NBH * (NS / NQBLK), 512, upd_smem>>>(q, k, v, out);
}

// round 5
// speedup vs baseline: 1.2016x; 1.2016x over previous
#include <cuda_runtime.h>
#include <cstdint>

#define B_   4
#define L_   2048
#define H_   8
#define D_   64
#define NS   40
#define NBH  (B_*H_)
#define NKC  8          // key chunks for M
#define KSUB 256        // keys per sub-chunk
#define QC   512        // queries per M block
#define PAD  68         // padded row (floats): 17 float4, conflict-free

__device__ int   g_idx[L_*NS];
__device__ int   g_lst[L_*NS];       // per-q samples sorted by chunk (stable)
__device__ int   g_qoff[L_*(NKC+1)];
__device__ float g_M[NBH*L_];
__device__ int   g_top[NBH*NS];

// ---------------- packed f32x2 helpers ----------------
__device__ __forceinline__ void fma2(unsigned long long& d,
                                     unsigned long long a, unsigned long long b) {
    asm("fma.rn.f32x2 %0, %1, %2, %0;" : "+l"(d) : "l"(a), "l"(b));
}
__device__ __forceinline__ unsigned long long pack2(float lo, float hi) {
    unsigned long long r;
    asm("mov.b64 %0, {%1, %2};" : "=l"(r) : "f"(lo), "f"(hi));
    return r;
}
__device__ __forceinline__ void unpack2(unsigned long long p, float& lo, float& hi) {
    asm("mov.b64 {%0, %1}, %2;" : "=f"(lo), "=f"(hi) : "l"(p));
}

// ---------------- threefry2x32 ----------------
__device__ __forceinline__ uint32_t rotl32(uint32_t x, int r) {
    return (x << r) | (x >> (32 - r));
}
__device__ __forceinline__ void threefry2x32(uint32_t k0, uint32_t k1,
                                             uint32_t c0, uint32_t c1,
                                             uint32_t& o0, uint32_t& o1) {
    uint32_t ks0 = k0, ks1 = k1, ks2 = k0 ^ k1 ^ 0x1BD11BDAu;
    uint32_t x0 = c0 + ks0, x1 = c1 + ks1;
#define TF_RND(R) { x0 += x1; x1 = rotl32(x1, R); x1 ^= x0; }
    TF_RND(13) TF_RND(15) TF_RND(26) TF_RND(6)  x0 += ks1; x1 += ks2 + 1u;
    TF_RND(17) TF_RND(29) TF_RND(16) TF_RND(24) x0 += ks2; x1 += ks0 + 2u;
    TF_RND(13) TF_RND(15) TF_RND(26) TF_RND(6)  x0 += ks0; x1 += ks1 + 3u;
    TF_RND(17) TF_RND(29) TF_RND(16) TF_RND(24) x0 += ks1; x1 += ks2 + 4u;
    TF_RND(13) TF_RND(15) TF_RND(26) TF_RND(6)  x0 += ks2; x1 += ks0 + 5u;
#undef TF_RND
    o0 = x0; o1 = x1;
}

// K0: partitionable threefry randint
__global__ void kernel_idx() {
    int i = blockIdx.x * blockDim.x + threadIdx.x;
    if (i >= L_ * NS) return;
    uint32_t k20, k21;
    threefry2x32(0u, 42u, 0u, 1u, k20, k21);
    uint32_t a, b;
    threefry2x32(k20, k21, 0u, (uint32_t)i, a, b);
    g_idx[i] = (int)((a ^ b) & 2047u);
}

// K0b: stable counting-sort by chunk (idx>>8), packed 8x8-bit counters (no LMEM)
__global__ void kernel_sortidx() {
    int qi = blockIdx.x * blockDim.x + threadIdx.x;
    if (qi >= L_) return;
    unsigned long long cnt = 0;
#pragma unroll 8
    for (int s = 0; s < NS; s++) {
        int vI = g_idx[qi * NS + s];
        cnt += 1ull << ((vI >> 8) * 8);
    }
    int off[NKC + 1];
    off[0] = 0;
#pragma unroll
    for (int c = 0; c < NKC; c++) off[c + 1] = off[c] + (int)((cnt >> (8 * c)) & 255);
#pragma unroll
    for (int c = 0; c <= NKC; c++) g_qoff[qi * (NKC + 1) + c] = off[c];
    unsigned long long pos = 0;
#pragma unroll
    for (int c = 0; c < NKC; c++) pos |= ((unsigned long long)off[c]) << (8 * c);
    for (int s = 0; s < NS; s++) {
        int vI = g_idx[qi * NS + s];
        int c = vI >> 8;
        int p = (int)((pos >> (8 * c)) & 255);
        g_lst[qi * NS + p] = vI;
        pos += 1ull << (8 * c);
    }
}

// K1: M = max - mean of sampled dots. Block=(b,h,q-chunk of 512). Thread owns 1 query.
__global__ __launch_bounds__(512, 1) void kernel_M(const float* __restrict__ q,
                                                   const float* __restrict__ k) {
    extern __shared__ float sh[];
    float* sQ = sh;                // QC * PAD
    float* sK = sh + QC * PAD;     // KSUB * PAD
    int qc = blockIdx.x & 3;
    int h  = (blockIdx.x >> 2) & 7;
    int b  = blockIdx.x >> 5;
    int t  = threadIdx.x;
    int qi = qc * QC + t;

    const float4* q4 = (const float4*)q;
    const float4* k4 = (const float4*)k;

    // stage Q chunk (coalesced) into padded smem
    for (int e = t; e < QC * 16; e += 512) {
        int r = e >> 4, c = e & 15;
        ((float4*)sQ)[r * 17 + c] =
            __ldg(&q4[(((size_t)b * L_ + qc * QC + r) * H_ + h) * 16 + c]);
    }
    __syncthreads();

    // own q row -> registers (conflict-free: bank = (t + c) pattern)
    ulonglong2 qreg[16];
    {
        const ulonglong2* sQu = (const ulonglong2*)sQ;
#pragma unroll
        for (int c = 0; c < 16; c++) qreg[c] = sQu[t * 17 + c];
    }

    float mx = -INFINITY, sm = 0.0f;
#pragma unroll 1
    for (int kc = 0; kc < NKC; kc++) {
        __syncthreads();
        for (int e = t; e < KSUB * 16; e += 512) {
            int r = e >> 4, c = e & 15;
            ((float4*)sK)[r * 17 + c] =
                __ldg(&k4[(((size_t)b * L_ + kc * KSUB + r) * H_ + h) * 16 + c]);
        }
        __syncthreads();
        int s0 = __ldg(&g_qoff[qi * (NKC + 1) + kc]);
        int s1 = __ldg(&g_qoff[qi * (NKC + 1) + kc + 1]);
        for (int s = s0; s < s1; s++) {
            int j = __ldg(&g_lst[qi * NS + s]) & (KSUB - 1);
            const ulonglong2* kr = (const ulonglong2*)sK + j * 17;
            unsigned long long acc = 0ull;
#pragma unroll
            for (int c = 0; c < 16; c++) {
                ulonglong2 kk = kr[c];
                fma2(acc, qreg[c].x, kk.x);
                fma2(acc, qreg[c].y, kk.y);
            }
            float lo, hi; unpack2(acc, lo, hi);
            float p = lo + hi;
            mx = fmaxf(mx, p);
            sm += p;
        }
    }
    g_M[(b * H_ + h) * L_ + qi] = mx - sm * (1.0f / (float)NS);
}

// K2: top-40 per (b,h), register-resident, tie-break lower index.
__global__ void kernel_topk() {
    int bh = blockIdx.x, t = threadIdx.x;   // 256 threads
    float vals[8];
#pragma unroll
    for (int i = 0; i < 8; i++) vals[i] = g_M[bh * L_ + t * 8 + i];

    __shared__ float wv[8];
    __shared__ int   wi[8];
    __shared__ int   sbi;
    int warp = t >> 5, lane = t & 31;

    for (int u = 0; u < NS; u++) {
        float bv = -INFINITY; int bi = 1 << 30;
#pragma unroll
        for (int i = 0; i < 8; i++) {
            if (vals[i] > bv) { bv = vals[i]; bi = t * 8 + i; }
        }
#pragma unroll
        for (int o = 16; o; o >>= 1) {
            float ov = __shfl_xor_sync(0xffffffffu, bv, o);
            int   oi = __shfl_xor_sync(0xffffffffu, bi, o);
            if (ov > bv || (ov == bv && oi < bi)) { bv = ov; bi = oi; }
        }
        if (lane == 0) { wv[warp] = bv; wi[warp] = bi; }
        __syncthreads();
        if (t == 0) {
            float fb = wv[0]; int fi = wi[0];
#pragma unroll
            for (int wd = 1; wd < 8; wd++) {
                if (wv[wd] > fb || (wv[wd] == fb && wi[wd] < fi)) { fb = wv[wd]; fi = wi[wd]; }
            }
            g_top[bh * NS + u] = fi;
            sbi = fi;
        }
        __syncthreads();
        int fi = sbi;
        if ((fi >> 3) == t) vals[fi & 7] = -INFINITY;
        __syncthreads();
    }
}

// K3: fused V_mean + broadcast-init. Block = (b,h). 512 threads.
__global__ __launch_bounds__(512) void kernel_vmean_init(const float* __restrict__ v,
                                                         float* __restrict__ out) {
    __shared__ float4 sred[512];
    __shared__ float4 vm4[16];
    int bh = blockIdx.x;
    int b = bh >> 3, h = bh & 7;
    int t = threadIdx.x;
    int d4 = t & 15, r = t >> 4;   // 32 rows in flight

    const float4* v4 = (const float4*)v;
    size_t base = ((size_t)b * L_) * (H_ * D_ / 4) + h * (D_ / 4) + d4;
    float4 acc = make_float4(0.f, 0.f, 0.f, 0.f);
#pragma unroll 8
    for (int it = 0; it < L_ / 32; it++) {
        float4 x = __ldg(&v4[base + (size_t)(it * 32 + r) * (H_ * D_ / 4)]);
        acc.x += x.x; acc.y += x.y; acc.z += x.z; acc.w += x.w;
    }
    sred[t] = acc;
    __syncthreads();
    for (int o = 256; o >= 16; o >>= 1) {
        if (t < o) {
            float4 a = sred[t], bb = sred[t + o];
            a.x += bb.x; a.y += bb.y; a.z += bb.z; a.w += bb.w;
            sred[t] = a;
        }
        __syncthreads();
    }
    if (t < 16) {
        float4 s = sred[t];
        const float inv = 1.0f / (float)L_;
        s.x *= inv; s.y *= inv; s.z *= inv; s.w *= inv;
        vm4[t] = s;
    }
    __syncthreads();
    float4* out4 = (float4*)out;
    for (int e = t; e < L_ * 16; e += 512) {
        int l = e >> 4, c = e & 15;
        out4[(((size_t)b * L_ + l) * H_ + h) * 16 + c] = vm4[c];
    }
}

// K4: dense attention for 40 selected queries. Block=(bh, group of 8). 512 threads.
__global__ __launch_bounds__(512) void kernel_update(const float* __restrict__ q,
                                                     const float* __restrict__ k,
                                                     const float* __restrict__ v,
                                                     float* __restrict__ out) {
    extern __shared__ float sh[];
    float* s_sc   = sh;                     // 8 * 2048
    float* s_q    = s_sc + 8 * L_;          // 512
    float* s_vout = s_q + 512;              // 8*8*64 = 4096
    float* s_red  = s_vout + 4096;          // 32 (max[16], sum[16])

    int bx  = blockIdx.x;
    int bh  = bx / 5;
    int grp = bx % 5;
    int b = bh >> 3, h = bh & 7;
    int t = threadIdx.x;
    int w = t >> 5, lane = t & 31;

    // stage the 8 selected q rows (qidx fetched via L1, no reg array)
    {
        int i = t >> 6, d = t & 63;
        int qx = __ldg(&g_top[bh * NS + grp * 8 + i]);
        s_q[t] = q[(((size_t)b * L_ + qx) * H_ + h) * D_ + d];
    }
    __syncthreads();

    // scores: 8 q x 2048 k, packed f32x2
    const ulonglong2* k16 = (const ulonglong2*)k;
    const ulonglong2* q16 = (const ulonglong2*)s_q;
#pragma unroll 1
    for (int rep = 0; rep < 4; rep++) {
        int j = rep * 512 + t;
        const ulonglong2* kr = k16 + (((size_t)b * L_ + j) * H_ + h) * 16;
        unsigned long long acc2[8];
#pragma unroll
        for (int i = 0; i < 8; i++) acc2[i] = 0ull;
#pragma unroll
        for (int dv = 0; dv < 16; dv++) {
            ulonglong2 kv = kr[dv];
#pragma unroll
            for (int i = 0; i < 8; i++) {
                ulonglong2 qv = q16[i * 16 + dv];
                fma2(acc2[i], kv.x, qv.x);
                fma2(acc2[i], kv.y, qv.y);
            }
        }
#pragma unroll
        for (int i = 0; i < 8; i++) {
            float lo, hi; unpack2(acc2[i], lo, hi);
            s_sc[i * L_ + j] = (lo + hi) * 0.125f;
        }
    }
    __syncthreads();

    // warp-parallel softmax: row r = w>>1, half hf = w&1 (1024 elems each)
    {
        int r = w >> 1, hf = w & 1;
        float* sc = s_sc + r * L_ + hf * 1024;
        float m = -INFINITY;
#pragma unroll
        for (int i = 0; i < 32; i++) m = fmaxf(m, sc[i * 32 + lane]);
#pragma unroll
        for (int o = 16; o; o >>= 1) m = fmaxf(m, __shfl_xor_sync(0xffffffffu, m, o));
        if (lane == 0) s_red[w] = m;
        __syncthreads();
        float gm = fmaxf(s_red[r << 1], s_red[(r << 1) | 1]);
        float ssum = 0.0f;
#pragma unroll
        for (int i = 0; i < 32; i++) {
            int jj = i * 32 + lane;
            float e = __expf(sc[jj] - gm);
            sc[jj] = e;
            ssum += e;
        }
#pragma unroll
        for (int o = 16; o; o >>= 1) ssum += __shfl_xor_sync(0xffffffffu, ssum, o);
        if (lane == 0) s_red[16 + w] = ssum;
        __syncthreads();
    }

    // attn @ V, unnormalized, packed over j-pairs. thread: d = t&63, chunk c = t>>6
    int d = t & 63, c = t >> 6;
    unsigned long long accu[8];
#pragma unroll
    for (int i = 0; i < 8; i++) accu[i] = 0ull;
    const float* vb = v + ((size_t)b * L_ * H_) * D_ + h * D_ + d;
#pragma unroll 1
    for (int jj = 0; jj < 128; jj++) {
        int j0 = c * 256 + jj * 2;
        float v0 = __ldg(&vb[(size_t)j0 * (H_ * D_)]);
        float v1 = __ldg(&vb[(size_t)(j0 + 1) * (H_ * D_)]);
        unsigned long long vp = pack2(v0, v1);
#pragma unroll
        for (int i = 0; i < 8; i++) {
            unsigned long long ap = *(const unsigned long long*)(s_sc + i * L_ + j0);
            fma2(accu[i], ap, vp);
        }
    }
#pragma unroll
    for (int i = 0; i < 8; i++) {
        float lo, hi; unpack2(accu[i], lo, hi);
        s_vout[(i * 8 + c) * 64 + d] = lo + hi;
    }
    __syncthreads();

    // final cross-chunk reduce + normalize + write (one element per thread)
    {
        int i = t >> 6, dd = t & 63;
        float inv = 1.0f / (s_red[16 + (i << 1)] + s_red[16 + (i << 1) + 1]);
        float tot = 0.0f;
#pragma unroll
        for (int cc = 0; cc < 8; cc++) tot += s_vout[(i * 8 + cc) * 64 + dd];
        int qx = __ldg(&g_top[bh * NS + grp * 8 + i]);
        out[(((size_t)b * L_ + qx) * H_ + h) * D_ + dd] = tot * inv;
    }
}

extern "C" void kernel_launch(void* const* d_in, const int* in_sizes, int n_in,
                              void* d_out, int out_size) {
    const float* q = (const float*)d_in[0];
    const float* k = (const float*)d_in[1];
    const float* v = (const float*)d_in[2];
    float* out = (float*)d_out;

    static const size_t m_smem   = (size_t)(QC + KSUB) * PAD * sizeof(float);   // 208896
    static const size_t upd_smem = (size_t)(8 * L_ + 512 + 4096 + 32) * sizeof(float);
    cudaFuncSetAttribute(kernel_M, cudaFuncAttributeMaxDynamicSharedMemorySize, (int)m_smem);
    cudaFuncSetAttribute(kernel_update, cudaFuncAttributeMaxDynamicSharedMemorySize, (int)upd_smem);

    kernel_idx<<<(L_ * NS + 255) / 256, 256>>>();
    kernel_sortidx<<<(L_ + 255) / 256, 256>>>();
    kernel_vmean_init<<<NBH, 512>>>(v, out);
    kernel_M<<<B_ * H_ * (L_ / QC), 512, m_smem>>>(q, k);
    kernel_topk<<<NBH, 256>>>();
    kernel_update<<<NBH * 5, 512, upd_smem>>>(q, k, v, out);
}